// round 11
// baseline (speedup 1.0000x reference)
#include <cuda_runtime.h>
#include <cuda_bf16.h>
#include <math_constants.h>

#define NM 1024
#define HH 256
#define WW 256
#define HW (HH * WW)
#define NQ 8             // stats partial blocks per mask (32 rows each)

// Scratch (no cudaMalloc allowed). Fully overwritten every call.
__device__ unsigned g_pp[NQ * NM];   // packed bbox: (rmin,255-rmax,cmin,255-cmax); 0xFFFFFFFF = empty
__device__ unsigned g_pk[NQ * NM];   // packed counts: hi<<16 | lo
__device__ float    g_gated[NM];

// ---------------------------------------------------------------------------
// Kernel A (fused, fine-interleaved): linear grid of 16384 blocks, 256 thr,
// 32 KB of traffic per block for BOTH roles, period-2 role mixing:
//   lin % 2 == 1 -> zero-writer (32 KB of output)   [8192 blocks, 256 MB W]
//   lin % 2 == 0 -> stats partial (32 KB of logits) [8192 blocks, 256 MB R]
// Every scheduling wave carries a steady 1:1 byte-rate read/write mix; stats
// threads keep 8 independent float4 loads in flight (MLP=8).
// ---------------------------------------------------------------------------
__global__ void __launch_bounds__(256) stats_zero_kernel(const float* __restrict__ logits,
                                                         float* __restrict__ out) {
    const int lin = blockIdx.x;
    const int tid = threadIdx.x;
    const int idx = lin >> 1;                 // 0..8191 within role

    if (lin & 1) {
        // ---- zero-writer role: 32 KB = 8 float4/thread ----
        const int n    = idx & (NM - 1);
        const int half = idx >> 10;           // 0..7
        float4* __restrict__ o4 =
            reinterpret_cast<float4*>(out + (size_t)n * HW + (size_t)half * 8192);
        const float4 z = make_float4(0.f, 0.f, 0.f, 0.f);
#pragma unroll
        for (int k = 0; k < 8; k++) o4[k * 256 + tid] = z;
        return;
    }

    // ---- stats role: 32 rows of one mask ----
    const int n    = idx & (NM - 1);
    const int q    = idx >> 10;               // 0..7
    const int tx   = tid & 63;
    const int ty   = tid >> 6;
    const int col0 = tx * 4;
    const int r0   = q * 32 + ty * 8;

    const float4* __restrict__ base =
        reinterpret_cast<const float4*>(logits + (size_t)n * HW) + tx;

    float4 v0 = base[(size_t)(r0 + 0) * (WW / 4)];
    float4 v1 = base[(size_t)(r0 + 1) * (WW / 4)];
    float4 v2 = base[(size_t)(r0 + 2) * (WW / 4)];
    float4 v3 = base[(size_t)(r0 + 3) * (WW / 4)];
    float4 v4 = base[(size_t)(r0 + 4) * (WW / 4)];
    float4 v5 = base[(size_t)(r0 + 5) * (WW / 4)];
    float4 v6 = base[(size_t)(r0 + 6) * (WW / 4)];
    float4 v7 = base[(size_t)(r0 + 7) * (WW / 4)];

    unsigned pk = 0;          // hi<<16 | lo
    int rmin_t = 255;
    int rmax_t = 0;
    unsigned cm4 = 0;

#define PROC(v, r)                                                             \
    {                                                                          \
        float mn = fminf(fminf(v.x, v.y), fminf(v.z, v.w));                    \
        float mx = fmaxf(fmaxf(v.x, v.y), fmaxf(v.z, v.w));                    \
        if (mx > -1.f) {                                                       \
            if (mn > 1.f) {                                                    \
                pk += 0x00040004u;                                             \
                rmin_t = min(rmin_t, r);                                       \
                rmax_t = r;                                                    \
                cm4 |= 0xFu;                                                   \
            } else {                                                           \
                int h = (v.x > 1.f) + (v.y > 1.f) + (v.z > 1.f) + (v.w > 1.f); \
                int l = (v.x > -1.f) + (v.y > -1.f) + (v.z > -1.f) +           \
                        (v.w > -1.f);                                          \
                pk += ((unsigned)h << 16) + (unsigned)l;                       \
                unsigned m = (v.x > 0.f) | ((v.y > 0.f) << 1) |                \
                             ((v.z > 0.f) << 2) | ((v.w > 0.f) << 3);          \
                if (m) {                                                       \
                    rmin_t = min(rmin_t, r);                                   \
                    rmax_t = r;                                                \
                    cm4 |= m;                                                  \
                }                                                              \
            }                                                                  \
        }                                                                      \
    }

    PROC(v0, r0 + 0)
    PROC(v1, r0 + 1)
    PROC(v2, r0 + 2)
    PROC(v3, r0 + 3)
    PROC(v4, r0 + 4)
    PROC(v5, r0 + 5)
    PROC(v6, r0 + 6)
    PROC(v7, r0 + 7)
#undef PROC

    // Pack bbox into byte-min-reducible word (255 = neutral per byte).
    unsigned p;
    if (cm4) {
        int cmin_t = col0 + (__ffs(cm4) - 1);
        int cmax_t = col0 + (31 - __clz(cm4));
        p = ((unsigned)rmin_t << 24) | ((unsigned)(255 - rmax_t) << 16) |
            ((unsigned)cmin_t << 8) | (unsigned)(255 - cmax_t);
    } else {
        p = 0xFFFFFFFFu;   // empty
    }

    // warp reduce: byte-wise min for bbox, packed add for counts
#pragma unroll
    for (int o = 16; o > 0; o >>= 1) {
        p  = __vminu4(p, __shfl_down_sync(0xffffffffu, p, o));
        pk += __shfl_down_sync(0xffffffffu, pk, o);
    }

    __shared__ unsigned s_p[8], s_pk[8];
    const int warp = tid >> 5;
    if ((tid & 31) == 0) { s_p[warp] = p; s_pk[warp] = pk; }
    __syncthreads();
    if (tid == 0) {
        unsigned P = s_p[0], K = s_pk[0];
#pragma unroll
        for (int w = 1; w < 8; w++) { P = __vminu4(P, s_p[w]); K += s_pk[w]; }
        const int gidx = q * NM + n;
        g_pp[gidx] = P;
        g_pk[gidx] = K;
    }
}

// ---------------------------------------------------------------------------
// Kernel B: single block (1024 threads). Merge partials, build boxes+validity,
// compact valid candidates, O(V^2) rank (few barriers), NMS via suppression
// bitmasks (V<=256) or iterative fallback.
// ---------------------------------------------------------------------------
__global__ void __launch_bounds__(1024) nms_kernel(const float* __restrict__ iou,
                                                   float* __restrict__ out_keep,
                                                   float* __restrict__ out_boxes,
                                                   int write_extra) {
    __shared__ float4 s_bx[NM];                // boxes in ORIGINAL index order
    __shared__ float  s_csc[NM];               // compacted scores (unsorted)
    __shared__ int    s_cid[NM];               // compacted original idx (unsorted)
    __shared__ float  s_sc[NM];                // rank-sorted scores
    __shared__ int    s_ord[NM];               // rank-sorted original idx
    __shared__ float  s_area[NM];              // area per sorted candidate
    __shared__ unsigned s_sup[256 * 8];        // suppression bitmask rows (V<=256)
    __shared__ unsigned s_live[8];
    __shared__ unsigned char s_keep[NM];       // keep flags (sorted order)
    __shared__ int s_cnt;

    const int tid = threadIdx.x;

    // ---- merge NQ partials ----
    unsigned P = 0xFFFFFFFFu, K = 0;
#pragma unroll
    for (int q = 0; q < NQ; q++) {
        const int idx = q * NM + tid;
        P = __vminu4(P, g_pp[idx]);
        K += g_pk[idx];
    }
    const int hi = (int)(K >> 16);
    const int lo = (int)(K & 0xFFFFu);

    float4 box;
    if (P == 0xFFFFFFFFu) {
        box = make_float4(0.f, 0.f, 0.f, 0.f);  // empty mask -> zeros
    } else {
        box = make_float4((float)((P >> 8) & 0xFF),          // left  = cmin
                          (float)(P >> 24),                  // top   = rmin
                          (float)(255 - (P & 0xFF)),         // right = cmax
                          (float)(255 - ((P >> 16) & 0xFF)));// bottom= rmax
    }
    s_bx[tid] = box;

    const float ip   = iou[tid];
    const float stab = (float)hi / fmaxf((float)lo, 1.0f);
    const bool  valid = (ip > 0.88f) && (stab >= 0.95f);

    if (tid == 0) s_cnt = 0;
    __syncthreads();
    int pos = -1;
    if (valid) pos = atomicAdd(&s_cnt, 1);
    if (pos >= 0) { s_csc[pos] = ip; s_cid[pos] = tid; }
    __syncthreads();
    const int V = s_cnt;

    if (V > 0) {
        // ---- O(V^2) ranking: deterministic sort without bitonic barriers ----
        if (tid < V) {
            const float ms = s_csc[tid];
            const int   mi = s_cid[tid];
            int rank = 0;
            for (int j = 0; j < V; j++) {
                float sj = s_csc[j];
                rank += (sj > ms) | ((sj == ms) & (s_cid[j] < mi));
            }
            s_sc[rank] = ms;
            s_ord[rank] = mi;
        }
        __syncthreads();

        if (tid < V) {
            float4 b = s_bx[s_ord[tid]];
            s_area[tid] = fmaxf(b.z - b.x, 0.f) * fmaxf(b.w - b.y, 0.f);
        }
        __syncthreads();

        if (V <= 256) {
            // ---- parallel suppression-matrix build ----
            if (tid < V) {
                const float4 bi = s_bx[s_ord[tid]];
                const float  ai = s_area[tid];
                unsigned w[8] = {0, 0, 0, 0, 0, 0, 0, 0};
                for (int j = tid + 1; j < V; j++) {
                    const float4 bj = s_bx[s_ord[j]];
                    float x0 = fmaxf(bi.x, bj.x), y0 = fmaxf(bi.y, bj.y);
                    float x1 = fminf(bi.z, bj.z), y1 = fminf(bi.w, bj.w);
                    float inter = fmaxf(x1 - x0, 0.f) * fmaxf(y1 - y0, 0.f);
                    float v = inter / fmaxf(ai + s_area[j] - inter, 1e-6f);
                    if (v > 0.7f) w[j >> 5] |= 1u << (j & 31);
                }
#pragma unroll
                for (int k = 0; k < 8; k++) s_sup[tid * 8 + k] = w[k];
            }
            __syncthreads();

            // ---- serial greedy resolution over bitmasks ----
            if (tid == 0) {
                unsigned live[8];
#pragma unroll
                for (int k = 0; k < 8; k++) {
                    int rem = V - k * 32;
                    live[k] = (rem >= 32) ? 0xffffffffu
                                          : (rem > 0 ? ((1u << rem) - 1u) : 0u);
                }
                for (int i = 0; i < V; i++) {
                    if ((live[i >> 5] >> (i & 31)) & 1u) {
#pragma unroll
                        for (int k = 0; k < 8; k++) live[k] &= ~s_sup[i * 8 + k];
                    }
                }
#pragma unroll
                for (int k = 0; k < 8; k++) s_live[k] = live[k];
            }
            __syncthreads();
            if (tid < V)
                s_keep[tid] = (s_live[tid >> 5] >> (tid & 31)) & 1u;
        } else {
            // ---- fallback: iterative greedy (rare) ----
            s_keep[tid] = (tid < V) ? 1 : 0;
            __syncthreads();
            float4 mb = make_float4(0, 0, 0, 0);
            float  ma = 0.f;
            if (tid < V) { mb = s_bx[s_ord[tid]]; ma = s_area[tid]; }
            for (int i = 0; i < V; i++) {
                if (tid < V && s_keep[i] && tid > i && s_keep[tid]) {
                    float4 pb = s_bx[s_ord[i]];
                    float x0 = fmaxf(pb.x, mb.x), y0 = fmaxf(pb.y, mb.y);
                    float x1 = fminf(pb.z, mb.z), y1 = fminf(pb.w, mb.w);
                    float inter = fmaxf(x1 - x0, 0.f) * fmaxf(y1 - y0, 0.f);
                    float v = inter / fmaxf(s_area[i] + ma - inter, 1e-6f);
                    if (v > 0.7f) s_keep[tid] = 0;
                }
                __syncthreads();
            }
        }
    }

    // ---- outputs: defaults, then kept overrides (ordered by __syncthreads) ----
    g_gated[tid] = 0.f;
    if (write_extra) {
        out_keep[tid] = 0.f;
        reinterpret_cast<float4*>(out_boxes)[tid] = s_bx[tid];
    }
    __syncthreads();
    if (tid < V && s_keep[tid]) {
        const int oi = s_ord[tid];
        g_gated[oi] = s_sc[tid];
        if (write_extra) out_keep[oi] = 1.f;
    }
}

// ---------------------------------------------------------------------------
// Kernel C: kept-only pass. Bulk output was pre-zeroed by the fused kernel;
// blocks with g==0 exit after one 4B load. Only ~6% of masks do the 32KB
// read + sigmoid + 32KB write. grid = (8, NM), 256 threads.
// ---------------------------------------------------------------------------
__global__ void __launch_bounds__(256) out_kernel(const float* __restrict__ logits,
                                                  float* __restrict__ out) {
    const int n = blockIdx.y;
    const float g = g_gated[n];
    if (g == 0.f) return;

    const int tid = threadIdx.x;
    const size_t base = (size_t)n * HW + (size_t)blockIdx.x * 8192;
    const float4* __restrict__ in4 = reinterpret_cast<const float4*>(logits + base);
    float4* __restrict__ o4 = reinterpret_cast<float4*>(out + base);

#pragma unroll
    for (int k = 0; k < 8; k++) {
        float4 v = in4[k * 256 + tid];
        float4 r;
        r.x = g / (1.f + __expf(-v.x));
        r.y = g / (1.f + __expf(-v.y));
        r.z = g / (1.f + __expf(-v.z));
        r.w = g / (1.f + __expf(-v.w));
        o4[k * 256 + tid] = r;
    }
}

// ---------------------------------------------------------------------------
extern "C" void kernel_launch(void* const* d_in, const int* in_sizes, int n_in,
                              void* d_out, int out_size) {
    const float* logits = (const float*)d_in[0];
    const float* iou    = (const float*)d_in[1];
    if (n_in >= 2 && in_sizes[0] == NM && in_sizes[1] == NM * HW) {
        logits = (const float*)d_in[1];
        iou    = (const float*)d_in[0];
    }

    float* out = (float*)d_out;
    const long long NHW = (long long)NM * HW;
    int write_extra = (out_size >= NHW + NM + NM * 4) ? 1 : 0;
    float* out_keep  = out + NHW;
    float* out_boxes = out + NHW + NM;

    stats_zero_kernel<<<16384, 256>>>(logits, out);
    nms_kernel<<<1, 1024>>>(iou, out_keep, out_boxes, write_extra);
    out_kernel<<<dim3(8, NM), 256>>>(logits, out);
}

// round 12
// speedup vs baseline: 1.0662x; 1.0662x over previous
#include <cuda_runtime.h>
#include <cuda_bf16.h>
#include <math_constants.h>

#define NM 1024
#define HH 256
#define WW 256
#define HW (HH * WW)
#define NQ 16            // stats partial blocks per mask

// Scratch (no cudaMalloc allowed). Fully overwritten every call.
__device__ unsigned g_pp[NQ * NM];   // packed bbox: (rmin,255-rmax,cmin,255-cmax); 0xFFFFFFFF = empty
__device__ unsigned g_pk[NQ * NM];   // packed counts: hi<<16 | lo
__device__ float    g_gated[NM];
__device__ int      g_klist[NM];     // kept mask indices (order arbitrary)
__device__ int      g_kcnt;          // number of kept masks

// ---------------------------------------------------------------------------
// Kernel A (fused, fine-interleaved) — R10 champion, unchanged.
// Linear grid of 24576 blocks, 256 thr.
//   lin % 3 == 2 -> zero-writer (32 KB of output)      [8192 blocks, 256 MB W]
//   lin % 3 <  2 -> stats partial (16 KB of logits)    [16384 blocks, 256 MB R]
// Period-3 mixing keeps every scheduling wave at a steady 2:1 read:write
// block mix (1:1 byte rate); ~80% DRAM, 6.35 TB/s aggregate.
// ---------------------------------------------------------------------------
__global__ void __launch_bounds__(256) stats_zero_kernel(const float* __restrict__ logits,
                                                         float* __restrict__ out) {
    const int lin = blockIdx.x;
    const int tid = threadIdx.x;
    const int rol = lin % 3;
    const int grp = lin / 3;

    if (rol == 2) {
        // ---- zero-writer role: 32 KB = 8 float4/thread ----
        const int zidx = grp;                 // 0..8191
        const int n    = zidx & (NM - 1);
        const int half = zidx >> 10;          // 0..7
        float4* __restrict__ o4 =
            reinterpret_cast<float4*>(out + (size_t)n * HW + (size_t)half * 8192);
        const float4 z = make_float4(0.f, 0.f, 0.f, 0.f);
#pragma unroll
        for (int k = 0; k < 8; k++) o4[k * 256 + tid] = z;
        return;
    }

    // ---- stats role ----
    const int sidx = grp * 2 + rol;           // 0..16383
    const int n    = sidx & (NM - 1);
    const int q    = sidx >> 10;              // 0..15
    const int tx   = tid & 63;
    const int ty   = tid >> 6;
    const int col0 = tx * 4;
    const int r0   = q * 16 + ty * 4;

    const float4* __restrict__ base =
        reinterpret_cast<const float4*>(logits + (size_t)n * HW) + tx;

    float4 v0 = base[(size_t)(r0 + 0) * (WW / 4)];
    float4 v1 = base[(size_t)(r0 + 1) * (WW / 4)];
    float4 v2 = base[(size_t)(r0 + 2) * (WW / 4)];
    float4 v3 = base[(size_t)(r0 + 3) * (WW / 4)];

    unsigned pk = 0;          // hi<<16 | lo
    int rmin_t = 255;
    int rmax_t = 0;
    unsigned cm4 = 0;

#define PROC(v, r)                                                             \
    {                                                                          \
        float mn = fminf(fminf(v.x, v.y), fminf(v.z, v.w));                    \
        float mx = fmaxf(fmaxf(v.x, v.y), fmaxf(v.z, v.w));                    \
        if (mx > -1.f) {                                                       \
            if (mn > 1.f) {                                                    \
                pk += 0x00040004u;                                             \
                rmin_t = min(rmin_t, r);                                       \
                rmax_t = r;                                                    \
                cm4 |= 0xFu;                                                   \
            } else {                                                           \
                int h = (v.x > 1.f) + (v.y > 1.f) + (v.z > 1.f) + (v.w > 1.f); \
                int l = (v.x > -1.f) + (v.y > -1.f) + (v.z > -1.f) +           \
                        (v.w > -1.f);                                          \
                pk += ((unsigned)h << 16) + (unsigned)l;                       \
                unsigned m = (v.x > 0.f) | ((v.y > 0.f) << 1) |                \
                             ((v.z > 0.f) << 2) | ((v.w > 0.f) << 3);          \
                if (m) {                                                       \
                    rmin_t = min(rmin_t, r);                                   \
                    rmax_t = r;                                                \
                    cm4 |= m;                                                  \
                }                                                              \
            }                                                                  \
        }                                                                      \
    }

    PROC(v0, r0 + 0)
    PROC(v1, r0 + 1)
    PROC(v2, r0 + 2)
    PROC(v3, r0 + 3)
#undef PROC

    // Pack bbox into byte-min-reducible word (255 = neutral per byte).
    unsigned p;
    if (cm4) {
        int cmin_t = col0 + (__ffs(cm4) - 1);
        int cmax_t = col0 + (31 - __clz(cm4));
        p = ((unsigned)rmin_t << 24) | ((unsigned)(255 - rmax_t) << 16) |
            ((unsigned)cmin_t << 8) | (unsigned)(255 - cmax_t);
    } else {
        p = 0xFFFFFFFFu;   // empty
    }

    // warp reduce: byte-wise min for bbox, packed add for counts
#pragma unroll
    for (int o = 16; o > 0; o >>= 1) {
        p  = __vminu4(p, __shfl_down_sync(0xffffffffu, p, o));
        pk += __shfl_down_sync(0xffffffffu, pk, o);
    }

    __shared__ unsigned s_p[8], s_pk[8];
    const int warp = tid >> 5;
    if ((tid & 31) == 0) { s_p[warp] = p; s_pk[warp] = pk; }
    __syncthreads();
    if (tid == 0) {
        unsigned P = s_p[0], K = s_pk[0];
#pragma unroll
        for (int w = 1; w < 8; w++) { P = __vminu4(P, s_p[w]); K += s_pk[w]; }
        const int idx = q * NM + n;
        g_pp[idx] = P;
        g_pk[idx] = K;
    }
}

// ---------------------------------------------------------------------------
// Kernel B: single block (1024 threads). Merge partials, build boxes+validity,
// compact valid candidates, O(V^2) rank (few barriers), NMS via suppression
// bitmasks (V<=256) or iterative fallback. Emits kept-mask list for kernel C.
// ---------------------------------------------------------------------------
__global__ void __launch_bounds__(1024) nms_kernel(const float* __restrict__ iou,
                                                   float* __restrict__ out_keep,
                                                   float* __restrict__ out_boxes,
                                                   int write_extra) {
    __shared__ float4 s_bx[NM];                // boxes in ORIGINAL index order
    __shared__ float  s_csc[NM];               // compacted scores (unsorted)
    __shared__ int    s_cid[NM];               // compacted original idx (unsorted)
    __shared__ float  s_sc[NM];                // rank-sorted scores
    __shared__ int    s_ord[NM];               // rank-sorted original idx
    __shared__ float  s_area[NM];              // area per sorted candidate
    __shared__ unsigned s_sup[256 * 8];        // suppression bitmask rows (V<=256)
    __shared__ unsigned s_live[8];
    __shared__ unsigned char s_keep[NM];       // keep flags (sorted order)
    __shared__ int s_cnt, s_kc;

    const int tid = threadIdx.x;

    // ---- merge NQ partials ----
    unsigned P = 0xFFFFFFFFu, K = 0;
#pragma unroll
    for (int q = 0; q < NQ; q++) {
        const int idx = q * NM + tid;
        P = __vminu4(P, g_pp[idx]);
        K += g_pk[idx];
    }
    const int hi = (int)(K >> 16);
    const int lo = (int)(K & 0xFFFFu);

    float4 box;
    if (P == 0xFFFFFFFFu) {
        box = make_float4(0.f, 0.f, 0.f, 0.f);  // empty mask -> zeros
    } else {
        box = make_float4((float)((P >> 8) & 0xFF),          // left  = cmin
                          (float)(P >> 24),                  // top   = rmin
                          (float)(255 - (P & 0xFF)),         // right = cmax
                          (float)(255 - ((P >> 16) & 0xFF)));// bottom= rmax
    }
    s_bx[tid] = box;

    const float ip   = iou[tid];
    const float stab = (float)hi / fmaxf((float)lo, 1.0f);
    const bool  valid = (ip > 0.88f) && (stab >= 0.95f);

    if (tid == 0) { s_cnt = 0; s_kc = 0; }
    __syncthreads();
    int pos = -1;
    if (valid) pos = atomicAdd(&s_cnt, 1);
    if (pos >= 0) { s_csc[pos] = ip; s_cid[pos] = tid; }
    __syncthreads();
    const int V = s_cnt;

    if (V > 0) {
        // ---- O(V^2) ranking: deterministic sort without bitonic barriers ----
        if (tid < V) {
            const float ms = s_csc[tid];
            const int   mi = s_cid[tid];
            int rank = 0;
            for (int j = 0; j < V; j++) {
                float sj = s_csc[j];
                rank += (sj > ms) | ((sj == ms) & (s_cid[j] < mi));
            }
            s_sc[rank] = ms;
            s_ord[rank] = mi;
        }
        __syncthreads();

        if (tid < V) {
            float4 b = s_bx[s_ord[tid]];
            s_area[tid] = fmaxf(b.z - b.x, 0.f) * fmaxf(b.w - b.y, 0.f);
        }
        __syncthreads();

        if (V <= 256) {
            // ---- parallel suppression-matrix build ----
            if (tid < V) {
                const float4 bi = s_bx[s_ord[tid]];
                const float  ai = s_area[tid];
                unsigned w[8] = {0, 0, 0, 0, 0, 0, 0, 0};
                for (int j = tid + 1; j < V; j++) {
                    const float4 bj = s_bx[s_ord[j]];
                    float x0 = fmaxf(bi.x, bj.x), y0 = fmaxf(bi.y, bj.y);
                    float x1 = fminf(bi.z, bj.z), y1 = fminf(bi.w, bj.w);
                    float inter = fmaxf(x1 - x0, 0.f) * fmaxf(y1 - y0, 0.f);
                    float v = inter / fmaxf(ai + s_area[j] - inter, 1e-6f);
                    if (v > 0.7f) w[j >> 5] |= 1u << (j & 31);
                }
#pragma unroll
                for (int k = 0; k < 8; k++) s_sup[tid * 8 + k] = w[k];
            }
            __syncthreads();

            // ---- serial greedy resolution over bitmasks ----
            if (tid == 0) {
                unsigned live[8];
#pragma unroll
                for (int k = 0; k < 8; k++) {
                    int rem = V - k * 32;
                    live[k] = (rem >= 32) ? 0xffffffffu
                                          : (rem > 0 ? ((1u << rem) - 1u) : 0u);
                }
                for (int i = 0; i < V; i++) {
                    if ((live[i >> 5] >> (i & 31)) & 1u) {
#pragma unroll
                        for (int k = 0; k < 8; k++) live[k] &= ~s_sup[i * 8 + k];
                    }
                }
#pragma unroll
                for (int k = 0; k < 8; k++) s_live[k] = live[k];
            }
            __syncthreads();
            if (tid < V)
                s_keep[tid] = (s_live[tid >> 5] >> (tid & 31)) & 1u;
        } else {
            // ---- fallback: iterative greedy (rare) ----
            s_keep[tid] = (tid < V) ? 1 : 0;
            __syncthreads();
            float4 mb = make_float4(0, 0, 0, 0);
            float  ma = 0.f;
            if (tid < V) { mb = s_bx[s_ord[tid]]; ma = s_area[tid]; }
            for (int i = 0; i < V; i++) {
                if (tid < V && s_keep[i] && tid > i && s_keep[tid]) {
                    float4 pb = s_bx[s_ord[i]];
                    float x0 = fmaxf(pb.x, mb.x), y0 = fmaxf(pb.y, mb.y);
                    float x1 = fminf(pb.z, mb.z), y1 = fminf(pb.w, mb.w);
                    float inter = fmaxf(x1 - x0, 0.f) * fmaxf(y1 - y0, 0.f);
                    float v = inter / fmaxf(s_area[i] + ma - inter, 1e-6f);
                    if (v > 0.7f) s_keep[tid] = 0;
                }
                __syncthreads();
            }
        }
    }

    // ---- outputs: defaults, kept overrides, kept list ----
    g_gated[tid] = 0.f;
    if (write_extra) {
        out_keep[tid] = 0.f;
        reinterpret_cast<float4*>(out_boxes)[tid] = s_bx[tid];
    }
    __syncthreads();
    if (tid < V && s_keep[tid]) {
        const int oi = s_ord[tid];
        g_gated[oi] = s_sc[tid];
        if (write_extra) out_keep[oi] = 1.f;
        const int slot = atomicAdd(&s_kc, 1);   // order-independent: disjoint regions
        g_klist[slot] = oi;
    }
    __syncthreads();
    if (tid == 0) g_kcnt = s_kc;
}

// ---------------------------------------------------------------------------
// Kernel C: kept-only pass via kept-list indirection. grid = (16, 256),
// 256 threads. Block (x, y) handles 4 KB-chunk x of kept masks y, y+256, ...
// Non-working blocks exit after a single load of g_kcnt.
// ---------------------------------------------------------------------------
__global__ void __launch_bounds__(256) out_kernel(const float* __restrict__ logits,
                                                  float* __restrict__ out) {
    const int kc = g_kcnt;
    const int tid = threadIdx.x;

    for (int s = blockIdx.y; s < kc; s += 256) {
        const int n = g_klist[s];
        const float g = g_gated[n];
        const size_t base = (size_t)n * HW + (size_t)blockIdx.x * 4096;
        const float4* __restrict__ in4 = reinterpret_cast<const float4*>(logits + base);
        float4* __restrict__ o4 = reinterpret_cast<float4*>(out + base);

#pragma unroll
        for (int k = 0; k < 4; k++) {
            float4 v = in4[k * 256 + tid];
            float4 r;
            r.x = g / (1.f + __expf(-v.x));
            r.y = g / (1.f + __expf(-v.y));
            r.z = g / (1.f + __expf(-v.z));
            r.w = g / (1.f + __expf(-v.w));
            o4[k * 256 + tid] = r;
        }
    }
}

// ---------------------------------------------------------------------------
extern "C" void kernel_launch(void* const* d_in, const int* in_sizes, int n_in,
                              void* d_out, int out_size) {
    const float* logits = (const float*)d_in[0];
    const float* iou    = (const float*)d_in[1];
    if (n_in >= 2 && in_sizes[0] == NM && in_sizes[1] == NM * HW) {
        logits = (const float*)d_in[1];
        iou    = (const float*)d_in[0];
    }

    float* out = (float*)d_out;
    const long long NHW = (long long)NM * HW;
    int write_extra = (out_size >= NHW + NM + NM * 4) ? 1 : 0;
    float* out_keep  = out + NHW;
    float* out_boxes = out + NHW + NM;

    stats_zero_kernel<<<24576, 256>>>(logits, out);
    nms_kernel<<<1, 1024>>>(iou, out_keep, out_boxes, write_extra);
    out_kernel<<<dim3(16, 256), 256>>>(logits, out);
}